// round 6
// baseline (speedup 1.0000x reference)
#include <cuda_runtime.h>
#include <cstdint>
#include <math.h>

#define B_  16
#define S_  4096
#define D_  512
#define DH_ 256
#define M_  (B_ * S_)   // 65536
#define CL_ 128
#define NC_ 32

// Scratch (device globals; allocation-free per harness rules)
__device__ float g_h[(size_t)M_ * DH_];        // 64 MB intermediate h
__device__ float g_carry[B_ * NC_ * D_];
__device__ float g_cvs[B_ * NC_ * D_];
__device__ float g_w1t[DH_ * D_];              // W1^T  [256,512] (n-major, k-contig)
__device__ float g_w2t[D_ * DH_];              // W2^T  [512,256]

// ===========================================================================
// helpers
// ===========================================================================
__device__ __forceinline__ uint32_t smem_u32(const void* p) {
    uint32_t a;
    asm("{ .reg .u64 t; cvta.to.shared.u64 t, %1; cvt.u32.u64 %0, t; }"
        : "=r"(a) : "l"(p));
    return a;
}

__device__ __forceinline__ void cp16(uint32_t dst, const void* src) {
    asm volatile("cp.async.cg.shared.global [%0], [%1], 16;" :: "r"(dst), "l"(src));
}
#define CP_COMMIT() asm volatile("cp.async.commit_group;" ::: "memory")
#define CP_WAIT0()  asm volatile("cp.async.wait_group 0;" ::: "memory")

#define LDSM_X4(r0, r1, r2, r3, addr) \
    asm volatile("ldmatrix.sync.aligned.m8n8.x4.shared.b16 {%0,%1,%2,%3}, [%4];" \
        : "=r"(r0), "=r"(r1), "=r"(r2), "=r"(r3) : "r"(addr))

__device__ __forceinline__ float softplus_f(float z) {
    return fmaxf(z, 0.f) + log1pf(expf(-fabsf(z)));
}

// ===========================================================================
// GARCH carry pass: per (b, chunk, d) scan 128 returns -> chunk carry only.
// ===========================================================================
__global__ void __launch_bounds__(256) garch_carry_kernel(
    const float* __restrict__ ret,
    const float* __restrict__ pa, const float* __restrict__ pb,
    const float* __restrict__ pw)
{
    const int g = blockIdx.x;
    const int d = ((g & 1) << 8) + threadIdx.x;
    const int c = (g >> 1) & (NC_ - 1);
    const int b = g >> 6;
    const float alpha = pa[0], beta = pb[0], omega = pw[0];
    const float* rp = ret + ((size_t)b * S_ + (size_t)c * CL_) * D_ + d;
    float p = 0.f;
#pragma unroll 8
    for (int k = 0; k < CL_; ++k) {
        float r = rp[(size_t)k * D_];
        p = fmaf(beta, p, fmaf(alpha, r * r, omega));
    }
    g_carry[(((b << 5) + c) << 9) + d] = p;
}

// ===========================================================================
// GARCH scan: preload all 32 carries (MLP=32), then register scan.
// cvs[c] = beta^128 * cvs[c-1] + carry[c-1]; cvs[0]=0.01
// ===========================================================================
__global__ void __launch_bounds__(256) garch_scan_kernel(const float* __restrict__ pb)
{
    const int t = blockIdx.x * 256 + threadIdx.x;
    const int b = t >> 9;
    const int d = t & (D_ - 1);
    const float beta = pb[0];
    float A = 1.f;
#pragma unroll
    for (int i = 0; i < CL_; ++i) A *= beta;

    float ca[NC_];
#pragma unroll
    for (int c = 0; c < NC_; ++c)
        ca[c] = g_carry[(((b << 5) + c) << 9) + d];

    float cvs = 0.01f;
#pragma unroll
    for (int c = 0; c < NC_; ++c) {
        g_cvs[(((b << 5) + c) << 9) + d] = cvs;
        cvs = fmaf(A, cvs, ca[c]);
    }
}

// ===========================================================================
// Weight transpose [K,N] -> [N,K]
// ===========================================================================
__global__ void transpose_kernel(const float* __restrict__ src, float* __restrict__ dst,
                                 int K, int N)
{
    __shared__ float t[32][33];
    const int kb = blockIdx.x * 32, nb = blockIdx.y * 32;
    for (int i = threadIdx.y; i < 32; i += 8)
        t[i][threadIdx.x] = src[(size_t)(kb + i) * N + nb + threadIdx.x];
    __syncthreads();
    for (int i = threadIdx.y; i < 32; i += 8)
        dst[(size_t)(nb + i) * K + kb + threadIdx.x] = t[threadIdx.x][i];
}

// ===========================================================================
// TF32 mma.sync GEMM with ldmatrix feed. 128x128 tile, BK=32, 8 warps,
// 2-stage cp.async ring. EPI==1: after mainloop, reuse stage smem to scan
// the exact GARCH recurrence from the block's ret tile (seeded by cvs),
// then softplus(out) * cv in the epilogue.
// ===========================================================================
#define BK 32
#define ROWB 144                          // GEMM smem row stride (bytes)
#define TILE_BYTES (128 * ROWB)           // 18432
#define STAGE_BYTES (2 * TILE_BYTES)      // 36864
#define SMEM_BYTES (2 * STAGE_BYTES)      // 73728
#define CVSTR 132                         // cv/ret smem row stride (floats)

template <int EPI>
__global__ void __launch_bounds__(256, 2) gemm_tc(
    const float* __restrict__ A, const float* __restrict__ Bt,
    const float* __restrict__ bias,
    const float* __restrict__ RET, const float* __restrict__ CVS,
    const float* __restrict__ pa, const float* __restrict__ pb,
    const float* __restrict__ pw,
    float* __restrict__ C, const int N, const int K)
{
    extern __shared__ char smraw[];
    const uint32_t sbase = smem_u32(smraw);
    float* cv_sm = (float*)smraw;          // overlays stage buffers post-mainloop
    __shared__ float bias_sm[128];

    const int tid  = threadIdx.x;
    const int lane = tid & 31;
    const int warp = tid >> 5;
    const int wm   = (warp >> 2) * 64;    // 2x4 warp grid, 64x32 per warp
    const int wn   = (warp & 3) * 32;
    const int gid  = lane >> 2;
    const int tig  = lane & 3;
    const int bm0  = blockIdx.y * 128;
    const int bn0  = blockIdx.x * 128;
    const int nk   = K / BK;

    if (tid < 128) bias_sm[tid] = bias[bn0 + tid];

    float acc[4][4][4];
#pragma unroll
    for (int mt = 0; mt < 4; ++mt)
#pragma unroll
        for (int nt = 0; nt < 4; ++nt)
#pragma unroll
            for (int i = 0; i < 4; ++i) acc[mt][nt][i] = 0.f;

    auto load_stage = [&](int kt, int st) {
        const uint32_t tb = sbase + st * STAGE_BYTES;
#pragma unroll
        for (int i = 0; i < 4; ++i) {
            const int id = tid + i * 256;
            const int r = id >> 3, s = id & 7;
            cp16(tb + r * ROWB + s * 16,
                 A + (size_t)(bm0 + r) * K + kt * BK + s * 4);
        }
#pragma unroll
        for (int i = 0; i < 4; ++i) {
            const int id = tid + i * 256;
            const int r = id >> 3, s = id & 7;
            cp16(tb + TILE_BYTES + r * ROWB + s * 16,
                 Bt + (size_t)(bn0 + r) * K + kt * BK + s * 4);
        }
        CP_COMMIT();
    };

    const int half = lane >> 3;
    const uint32_t laneA = (uint32_t)((wm + (lane & 7) + (half & 1) * 8) * ROWB
                                      + (half >> 1) * 16);
    const uint32_t laneB = (uint32_t)((wn + (lane & 7)) * ROWB + (lane >> 3) * 16);

    load_stage(0, 0);

    for (int kt = 0; kt < nk; ++kt) {
        CP_WAIT0();
        __syncthreads();
        const uint32_t aB = sbase + (kt & 1) * STAGE_BYTES;
        const uint32_t bB = aB + TILE_BYTES;
        if (kt + 1 < nk) load_stage(kt + 1, (kt + 1) & 1);

#pragma unroll
        for (int qp = 0; qp < 2; ++qp) {
            uint32_t bf[4][4];
#pragma unroll
            for (int nt = 0; nt < 4; ++nt)
                LDSM_X4(bf[nt][0], bf[nt][1], bf[nt][2], bf[nt][3],
                        bB + laneB + nt * (8 * ROWB) + qp * 64);
#pragma unroll
            for (int q2 = 0; q2 < 2; ++q2) {
                const int q = 2 * qp + q2;
                uint32_t af[4][4];
#pragma unroll
                for (int mt = 0; mt < 4; ++mt)
                    LDSM_X4(af[mt][0], af[mt][1], af[mt][2], af[mt][3],
                            aB + laneA + mt * (16 * ROWB) + q * 32);
#pragma unroll
                for (int mt = 0; mt < 4; ++mt)
#pragma unroll
                    for (int nt = 0; nt < 4; ++nt)
                        asm volatile(
                            "mma.sync.aligned.m16n8k8.row.col.f32.tf32.tf32.f32 "
                            "{%0,%1,%2,%3},{%4,%5,%6,%7},{%8,%9},{%0,%1,%2,%3};"
                            : "+f"(acc[mt][nt][0]), "+f"(acc[mt][nt][1]),
                              "+f"(acc[mt][nt][2]), "+f"(acc[mt][nt][3])
                            : "r"(af[mt][0]), "r"(af[mt][1]),
                              "r"(af[mt][2]), "r"(af[mt][3]),
                              "r"(bf[nt][2 * q2]), "r"(bf[nt][2 * q2 + 1]));
            }
        }
    }

    // ---- EPI==1: in-block GARCH scan over reused stage smem ----
    if (EPI == 1) {
        __syncthreads();                   // all LDSM on stage buffers done
        const float* Rg = RET + (size_t)bm0 * D_ + bn0;
#pragma unroll
        for (int i = 0; i < 16; ++i) {     // 4096 16B chunks
            const int id = tid + i * 256;
            const int r = id >> 5, s = id & 31;
            cp16(sbase + (uint32_t)(r * (CVSTR * 4) + s * 16),
                 Rg + (size_t)r * D_ + s * 4);
        }
        CP_COMMIT();
        CP_WAIT0();
        __syncthreads();

        if (tid < 128) {
            const float alpha = pa[0], beta = pb[0], omega = pw[0];
            const int b = bm0 >> 12;
            const int chunk = (bm0 >> 7) & (NC_ - 1);
            const size_t cvsbase = (size_t)(((b << 5) + chunk) << 9);
            float p = CVS[cvsbase + bn0 + tid];
#pragma unroll 8
            for (int k = 0; k < CL_; ++k) {
                const int idx = k * CVSTR + tid;
                float r = cv_sm[idx];
                cv_sm[idx] = p;
                p = fmaf(beta, p, fmaf(alpha, r * r, omega));
            }
        }
        __syncthreads();
    }

    // ---- Epilogue ----
#pragma unroll
    for (int mt = 0; mt < 4; ++mt) {
#pragma unroll
        for (int i = 0; i < 2; ++i) {
            const int rl  = wm + mt * 16 + gid + i * 8;
            const int row = bm0 + rl;
#pragma unroll
            for (int nt = 0; nt < 4; ++nt) {
                const int cl = wn + nt * 8 + 2 * tig;
                float v0 = acc[mt][nt][2 * i + 0] + bias_sm[cl];
                float v1 = acc[mt][nt][2 * i + 1] + bias_sm[cl + 1];
                if (EPI == 0) {
                    v0 = fmaxf(v0, 0.f);
                    v1 = fmaxf(v1, 0.f);
                } else {
                    const float2 cv = *(const float2*)&cv_sm[rl * CVSTR + cl];
                    v0 = softplus_f(v0) * cv.x;
                    v1 = softplus_f(v1) * cv.y;
                }
                *(float2*)(C + (size_t)row * N + bn0 + cl) = make_float2(v0, v1);
            }
        }
    }
}

// ===========================================================================
extern "C" void kernel_launch(void* const* d_in, const int* in_sizes, int n_in,
                              void* d_out, int out_size)
{
    const float* x   = (const float*)d_in[0];
    const float* ret = (const float*)d_in[1];
    const float* al  = (const float*)d_in[2];
    const float* be  = (const float*)d_in[3];
    const float* om  = (const float*)d_in[4];
    const float* W1  = (const float*)d_in[5];
    const float* b1  = (const float*)d_in[6];
    const float* W2  = (const float*)d_in[7];
    const float* b2  = (const float*)d_in[8];
    float* out = (float*)d_out;

    float *h, *cvs, *w1t, *w2t;
    cudaGetSymbolAddress((void**)&h,   g_h);
    cudaGetSymbolAddress((void**)&cvs, g_cvs);
    cudaGetSymbolAddress((void**)&w1t, g_w1t);
    cudaGetSymbolAddress((void**)&w2t, g_w2t);

    cudaFuncSetAttribute(gemm_tc<0>, cudaFuncAttributeMaxDynamicSharedMemorySize, SMEM_BYTES);
    cudaFuncSetAttribute(gemm_tc<1>, cudaFuncAttributeMaxDynamicSharedMemorySize, SMEM_BYTES);

    transpose_kernel<<<dim3(D_ / 32, DH_ / 32), dim3(32, 8)>>>(W1, w1t, D_, DH_);
    transpose_kernel<<<dim3(DH_ / 32, D_ / 32), dim3(32, 8)>>>(W2, w2t, DH_, D_);
    garch_carry_kernel<<<B_ * NC_ * (D_ / 256), 256>>>(ret, al, be, om);
    garch_scan_kernel<<<(B_ * D_) / 256, 256>>>(be);
    gemm_tc<0><<<dim3(DH_ / 128, M_ / 128), 256, SMEM_BYTES>>>(
        x, w1t, b1, nullptr, nullptr, nullptr, nullptr, nullptr, h, DH_, D_);
    gemm_tc<1><<<dim3(D_ / 128, M_ / 128), 256, SMEM_BYTES>>>(
        h, w2t, b2, ret, cvs, al, be, om, out, D_, DH_);
}

// round 7
// speedup vs baseline: 1.0245x; 1.0245x over previous
#include <cuda_runtime.h>
#include <cstdint>
#include <math.h>

#define B_  16
#define S_  4096
#define D_  512
#define DH_ 256
#define M_  (B_ * S_)   // 65536
#define CL_ 128
#define NC_ 32

// Scratch (device globals; allocation-free per harness rules)
__device__ float g_h[(size_t)M_ * DH_];        // 64 MB intermediate h
__device__ float g_carry[B_ * NC_ * D_];
__device__ float g_cvs[B_ * NC_ * D_];
__device__ float g_w1t[DH_ * D_];              // W1^T  [256,512] (n-major, k-contig)
__device__ float g_w2t[D_ * DH_];              // W2^T  [512,256]

// ===========================================================================
// helpers
// ===========================================================================
__device__ __forceinline__ uint32_t smem_u32(const void* p) {
    uint32_t a;
    asm("{ .reg .u64 t; cvta.to.shared.u64 t, %1; cvt.u32.u64 %0, t; }"
        : "=r"(a) : "l"(p));
    return a;
}

__device__ __forceinline__ void cp16(uint32_t dst, const void* src) {
    asm volatile("cp.async.cg.shared.global [%0], [%1], 16;" :: "r"(dst), "l"(src));
}
#define CP_COMMIT() asm volatile("cp.async.commit_group;" ::: "memory")
#define CP_WAIT(n)  asm volatile("cp.async.wait_group %0;" :: "n"(n) : "memory")

#define LDSM_X4(r0, r1, r2, r3, addr) \
    asm volatile("ldmatrix.sync.aligned.m8n8.x4.shared.b16 {%0,%1,%2,%3}, [%4];" \
        : "=r"(r0), "=r"(r1), "=r"(r2), "=r"(r3) : "r"(addr))

__device__ __forceinline__ float softplus_f(float z) {
    return fmaxf(z, 0.f) + log1pf(expf(-fabsf(z)));
}

// ===========================================================================
// GARCH carry pass: per (b, chunk, d) scan 128 returns -> chunk carry only.
// ===========================================================================
__global__ void __launch_bounds__(256) garch_carry_kernel(
    const float* __restrict__ ret,
    const float* __restrict__ pa, const float* __restrict__ pb,
    const float* __restrict__ pw)
{
    const int g = blockIdx.x;
    const int d = ((g & 1) << 8) + threadIdx.x;
    const int c = (g >> 1) & (NC_ - 1);
    const int b = g >> 6;
    const float alpha = pa[0], beta = pb[0], omega = pw[0];
    const float* rp = ret + ((size_t)b * S_ + (size_t)c * CL_) * D_ + d;
    float p = 0.f;
#pragma unroll 8
    for (int k = 0; k < CL_; ++k) {
        float r = rp[(size_t)k * D_];
        p = fmaf(beta, p, fmaf(alpha, r * r, omega));
    }
    g_carry[(((b << 5) + c) << 9) + d] = p;
}

// ===========================================================================
// GARCH scan: preload all 32 carries (MLP=32), then register scan.
// ===========================================================================
__global__ void __launch_bounds__(256) garch_scan_kernel(const float* __restrict__ pb)
{
    const int t = blockIdx.x * 256 + threadIdx.x;
    const int b = t >> 9;
    const int d = t & (D_ - 1);
    const float beta = pb[0];
    float A = 1.f;
#pragma unroll
    for (int i = 0; i < CL_; ++i) A *= beta;

    float ca[NC_];
#pragma unroll
    for (int c = 0; c < NC_; ++c)
        ca[c] = g_carry[(((b << 5) + c) << 9) + d];

    float cvs = 0.01f;
#pragma unroll
    for (int c = 0; c < NC_; ++c) {
        g_cvs[(((b << 5) + c) << 9) + d] = cvs;
        cvs = fmaf(A, cvs, ca[c]);
    }
}

// ===========================================================================
// Weight transpose [K,N] -> [N,K]
// ===========================================================================
__global__ void transpose_kernel(const float* __restrict__ src, float* __restrict__ dst,
                                 int K, int N)
{
    __shared__ float t[32][33];
    const int kb = blockIdx.x * 32, nb = blockIdx.y * 32;
    for (int i = threadIdx.y; i < 32; i += 8)
        t[i][threadIdx.x] = src[(size_t)(kb + i) * N + nb + threadIdx.x];
    __syncthreads();
    for (int i = threadIdx.y; i < 32; i += 8)
        dst[(size_t)(nb + i) * K + kb + threadIdx.x] = t[threadIdx.x][i];
}

// ===========================================================================
// TF32 mma.sync GEMM, ldmatrix feed, 128x128 tile, BK=32, 8 warps,
// 3-stage cp.async ring (wait_group 1 steady state).
// Stage index remapped so the FINAL iteration uses physical slot 2; in that
// iteration (EPI==1) the ret tile is prefetched into dead slots 0-1, then the
// exact GARCH recurrence is scanned in smem (seeded by cvs) for the epilogue.
// ===========================================================================
#define BK 32
#define ROWB 144                          // GEMM smem row stride (bytes)
#define TILE_BYTES (128 * ROWB)           // 18432
#define STAGE_BYTES (2 * TILE_BYTES)      // 36864
#define NSTAGE 3
#define SMEM_BYTES (NSTAGE * STAGE_BYTES) // 110592
#define CVSTR 132                         // cv/ret smem row stride (floats)

template <int EPI>
__global__ void __launch_bounds__(256, 2) gemm_tc(
    const float* __restrict__ A, const float* __restrict__ Bt,
    const float* __restrict__ bias,
    const float* __restrict__ RET, const float* __restrict__ CVS,
    const float* __restrict__ pa, const float* __restrict__ pb,
    const float* __restrict__ pw,
    float* __restrict__ C, const int N, const int K)
{
    extern __shared__ char smraw[];
    const uint32_t sbase = smem_u32(smraw);
    float* cv_sm = (float*)smraw;          // overlays slots 0-1 post-mainloop
    __shared__ float bias_sm[128];

    const int tid  = threadIdx.x;
    const int lane = tid & 31;
    const int warp = tid >> 5;
    const int wm   = (warp >> 2) * 64;    // 2x4 warp grid, 64x32 per warp
    const int wn   = (warp & 3) * 32;
    const int gid  = lane >> 2;
    const int tig  = lane & 3;
    const int bm0  = blockIdx.y * 128;
    const int bn0  = blockIdx.x * 128;
    const int nk   = K / BK;
    const int OFF  = (2 - ((nk - 1) % 3) + 3) % 3;   // st(nk-1) == 2

    if (tid < 128) bias_sm[tid] = bias[bn0 + tid];

    float acc[4][4][4];
#pragma unroll
    for (int mt = 0; mt < 4; ++mt)
#pragma unroll
        for (int nt = 0; nt < 4; ++nt)
#pragma unroll
            for (int i = 0; i < 4; ++i) acc[mt][nt][i] = 0.f;

    auto load_stage = [&](int kt) {
        const uint32_t tb = sbase + (uint32_t)(((kt + OFF) % 3) * STAGE_BYTES);
#pragma unroll
        for (int i = 0; i < 4; ++i) {
            const int id = tid + i * 256;
            const int r = id >> 3, s = id & 7;
            cp16(tb + r * ROWB + s * 16,
                 A + (size_t)(bm0 + r) * K + kt * BK + s * 4);
        }
#pragma unroll
        for (int i = 0; i < 4; ++i) {
            const int id = tid + i * 256;
            const int r = id >> 3, s = id & 7;
            cp16(tb + TILE_BYTES + r * ROWB + s * 16,
                 Bt + (size_t)(bn0 + r) * K + kt * BK + s * 4);
        }
        CP_COMMIT();
    };

    const int half = lane >> 3;
    const uint32_t laneA = (uint32_t)((wm + (lane & 7) + (half & 1) * 8) * ROWB
                                      + (half >> 1) * 16);
    const uint32_t laneB = (uint32_t)((wn + (lane & 7)) * ROWB + (lane >> 3) * 16);

    load_stage(0);
    load_stage(1);

    for (int kt = 0; kt < nk; ++kt) {
        if (kt + 1 < nk) { CP_WAIT(1); } else { CP_WAIT(0); }
        __syncthreads();
        const uint32_t aB = sbase + (uint32_t)(((kt + OFF) % 3) * STAGE_BYTES);
        const uint32_t bB = aB + TILE_BYTES;
        if (kt + 2 < nk) load_stage(kt + 2);

        if (EPI == 1 && kt == nk - 1) {
            // final iter computes from slot 2; prefetch ret into slots 0-1
            const float* Rg = RET + (size_t)bm0 * D_ + bn0;
#pragma unroll
            for (int i = 0; i < 16; ++i) {     // 4096 16B chunks
                const int id = tid + i * 256;
                const int r = id >> 5, s = id & 31;
                cp16(sbase + (uint32_t)(r * (CVSTR * 4) + s * 16),
                     Rg + (size_t)r * D_ + s * 4);
            }
            CP_COMMIT();
        }

#pragma unroll
        for (int qp = 0; qp < 2; ++qp) {
            uint32_t bf[4][4];
#pragma unroll
            for (int nt = 0; nt < 4; ++nt)
                LDSM_X4(bf[nt][0], bf[nt][1], bf[nt][2], bf[nt][3],
                        bB + laneB + nt * (8 * ROWB) + qp * 64);
#pragma unroll
            for (int q2 = 0; q2 < 2; ++q2) {
                const int q = 2 * qp + q2;
                uint32_t af[4][4];
#pragma unroll
                for (int mt = 0; mt < 4; ++mt)
                    LDSM_X4(af[mt][0], af[mt][1], af[mt][2], af[mt][3],
                            aB + laneA + mt * (16 * ROWB) + q * 32);
#pragma unroll
                for (int mt = 0; mt < 4; ++mt)
#pragma unroll
                    for (int nt = 0; nt < 4; ++nt)
                        asm volatile(
                            "mma.sync.aligned.m16n8k8.row.col.f32.tf32.tf32.f32 "
                            "{%0,%1,%2,%3},{%4,%5,%6,%7},{%8,%9},{%0,%1,%2,%3};"
                            : "+f"(acc[mt][nt][0]), "+f"(acc[mt][nt][1]),
                              "+f"(acc[mt][nt][2]), "+f"(acc[mt][nt][3])
                            : "r"(af[mt][0]), "r"(af[mt][1]),
                              "r"(af[mt][2]), "r"(af[mt][3]),
                              "r"(bf[nt][2 * q2]), "r"(bf[nt][2 * q2 + 1]));
            }
        }
    }

    // ---- EPI==1: in-block GARCH scan over reused stage smem ----
    if (EPI == 1) {
        CP_WAIT(0);                        // ret tile arrived
        __syncthreads();                   // all LDSM done, smem visible
        if (tid < 128) {
            const float alpha = pa[0], beta = pb[0], omega = pw[0];
            const int b = bm0 >> 12;
            const int chunk = (bm0 >> 7) & (NC_ - 1);
            const size_t cvsbase = (size_t)(((b << 5) + chunk) << 9);
            float p = CVS[cvsbase + bn0 + tid];
#pragma unroll 8
            for (int k = 0; k < CL_; ++k) {
                const int idx = k * CVSTR + tid;
                float r = cv_sm[idx];
                cv_sm[idx] = p;
                p = fmaf(beta, p, fmaf(alpha, r * r, omega));
            }
        }
        __syncthreads();
    }

    // ---- Epilogue ----
#pragma unroll
    for (int mt = 0; mt < 4; ++mt) {
#pragma unroll
        for (int i = 0; i < 2; ++i) {
            const int rl  = wm + mt * 16 + gid + i * 8;
            const int row = bm0 + rl;
#pragma unroll
            for (int nt = 0; nt < 4; ++nt) {
                const int cl = wn + nt * 8 + 2 * tig;
                float v0 = acc[mt][nt][2 * i + 0] + bias_sm[cl];
                float v1 = acc[mt][nt][2 * i + 1] + bias_sm[cl + 1];
                if (EPI == 0) {
                    v0 = fmaxf(v0, 0.f);
                    v1 = fmaxf(v1, 0.f);
                } else {
                    const float2 cv = *(const float2*)&cv_sm[rl * CVSTR + cl];
                    v0 = softplus_f(v0) * cv.x;
                    v1 = softplus_f(v1) * cv.y;
                }
                *(float2*)(C + (size_t)row * N + bn0 + cl) = make_float2(v0, v1);
            }
        }
    }
}

// ===========================================================================
extern "C" void kernel_launch(void* const* d_in, const int* in_sizes, int n_in,
                              void* d_out, int out_size)
{
    const float* x   = (const float*)d_in[0];
    const float* ret = (const float*)d_in[1];
    const float* al  = (const float*)d_in[2];
    const float* be  = (const float*)d_in[3];
    const float* om  = (const float*)d_in[4];
    const float* W1  = (const float*)d_in[5];
    const float* b1  = (const float*)d_in[6];
    const float* W2  = (const float*)d_in[7];
    const float* b2  = (const float*)d_in[8];
    float* out = (float*)d_out;

    float *h, *cvs, *w1t, *w2t;
    cudaGetSymbolAddress((void**)&h,   g_h);
    cudaGetSymbolAddress((void**)&cvs, g_cvs);
    cudaGetSymbolAddress((void**)&w1t, g_w1t);
    cudaGetSymbolAddress((void**)&w2t, g_w2t);

    cudaFuncSetAttribute(gemm_tc<0>, cudaFuncAttributeMaxDynamicSharedMemorySize, SMEM_BYTES);
    cudaFuncSetAttribute(gemm_tc<1>, cudaFuncAttributeMaxDynamicSharedMemorySize, SMEM_BYTES);

    transpose_kernel<<<dim3(D_ / 32, DH_ / 32), dim3(32, 8)>>>(W1, w1t, D_, DH_);
    transpose_kernel<<<dim3(DH_ / 32, D_ / 32), dim3(32, 8)>>>(W2, w2t, DH_, D_);
    garch_carry_kernel<<<B_ * NC_ * (D_ / 256), 256>>>(ret, al, be, om);
    garch_scan_kernel<<<(B_ * D_) / 256, 256>>>(be);
    gemm_tc<0><<<dim3(DH_ / 128, M_ / 128), 256, SMEM_BYTES>>>(
        x, w1t, b1, nullptr, nullptr, nullptr, nullptr, nullptr, h, DH_, D_);
    gemm_tc<1><<<dim3(D_ / 128, M_ / 128), 256, SMEM_BYTES>>>(
        h, w2t, b2, ret, cvs, al, be, om, out, D_, DH_);
}